// round 3
// baseline (speedup 1.0000x reference)
#include <cuda_runtime.h>

// Problem constants
#define Bq  16
#define Cq  128
#define HWq 1024
#define Nq  16384   // B*H*W
#define Dq  64
#define Kq  8192

#define ZQ_ELEMS 1048576          // Nq*Dq  (z_q_st output, NCHW)
#define DIFF_OFF 1048576
#define IND_OFF  1048577

// ---- scratch (device globals; no allocation allowed) ----
__device__ float g_ze[Nq * Dq];   // projected+BN z_e, row-major [N, D]
__device__ float g_ce[Kq];        // ||e_k||^2
__device__ int   g_ind[Nq];       // argmin indices
__device__ float g_part[64];      // per-block partial sums for diff

// Packed dual fp32 FMA (sm_10x): d.lo += a.lo*b.lo ; d.hi += a.hi*b.hi
__device__ __forceinline__ void fma2(unsigned long long& d,
                                     unsigned long long a,
                                     unsigned long long b) {
    asm("fma.rn.f32x2 %0, %1, %2, %3;" : "=l"(d) : "l"(a), "l"(b), "l"(d));
}

// ============================================================
// Kernel A: z_e = BN(conv1x1(z))   [N, D] fp32
// Block: 32 n-rows, 256 threads. warp w owns d-range [8w, 8w+8), lane = n.
// ============================================================
__global__ __launch_bounds__(256) void k_proj(
    const float* __restrict__ z,   const float* __restrict__ w,
    const float* __restrict__ pb,  const float* __restrict__ gma,
    const float* __restrict__ bta, const float* __restrict__ rmn,
    const float* __restrict__ rvr)
{
    __shared__ float zsm[Cq * 32];   // [c][nn]
    __shared__ float wsm[Dq * Cq];   // [d][c]  (reads are warp-uniform -> broadcast)
    int tid = threadIdx.x;
    int n0  = blockIdx.x * 32;
    int b   = n0 >> 10, hw0 = n0 & 1023;

#pragma unroll
    for (int i = 0; i < 16; i++) {
        int idx = tid + i * 256;
        int c = idx >> 5, nn = idx & 31;
        zsm[idx] = z[(b * Cq + c) * HWq + hw0 + nn];
    }
#pragma unroll
    for (int i = 0; i < 32; i++) wsm[tid + i * 256] = w[tid + i * 256];
    __syncthreads();

    int lane = tid & 31, wd = tid >> 5;
    int d0 = wd * 8;
    float acc[8];
#pragma unroll
    for (int j = 0; j < 8; j++) acc[j] = 0.f;

#pragma unroll 4
    for (int c = 0; c < Cq; c++) {
        float a = zsm[c * 32 + lane];
#pragma unroll
        for (int j = 0; j < 8; j++)
            acc[j] = fmaf(a, wsm[(d0 + j) * Cq + c], acc[j]);
    }

    float o[8];
#pragma unroll
    for (int j = 0; j < 8; j++) {
        int d = d0 + j;
        float sc = gma[d] * (1.0f / sqrtf(rvr[d] + 1e-5f));
        float sh = bta[d] - rmn[d] * sc;
        o[j] = (acc[j] + pb[d]) * sc + sh;
    }
    float* dst = g_ze + (size_t)(n0 + lane) * Dq + d0;
    ((float4*)dst)[0] = make_float4(o[0], o[1], o[2], o[3]);
    ((float4*)dst)[1] = make_float4(o[4], o[5], o[6], o[7]);
}

// ============================================================
// Kernel B: ce[k] = ||embed[k]||^2   (one warp per k)
// ============================================================
__global__ __launch_bounds__(256) void k_ce(const float* __restrict__ embed) {
    int gw   = (blockIdx.x * 256 + threadIdx.x) >> 5;
    int lane = threadIdx.x & 31;
    float2 v = ((const float2*)embed)[gw * 32 + lane];
    float s = v.x * v.x + v.y * v.y;
#pragma unroll
    for (int o = 16; o; o >>= 1) s += __shfl_xor_sync(0xffffffffu, s, o);
    if (lane == 0) g_ce[gw] = s;
}

// ============================================================
// Kernel C: argmin_k ( (szz - 2*dot) + ce[k] )   -- the 17.2 GFLOP GEMM
// Block: 64 n-rows x all K.  256 threads: ty=tid/32 -> 8 n-rows, tx -> 2 k's
// per 64-k chunk.  f32x2 packed FMAs over the D=64 reduction (32 pairs).
// ============================================================
__global__ __launch_bounds__(256, 2) void k_argmin(const float* __restrict__ embed)
{
    __shared__ float  zs[64 * Dq];     // z_e tile, [n][d]
    __shared__ float2 es[32 * 65];     // embed chunk, [dpair][k], +1 f2 pad
    __shared__ float  szz[64];

    int tid = threadIdx.x;
    int tx  = tid & 31, ty = tid >> 5;
    int n0  = blockIdx.x * 64;

    {   // load z_e tile (4096 floats)
        const float4* src = (const float4*)(g_ze + (size_t)n0 * Dq);
        float4* dst4 = (float4*)zs;
#pragma unroll
        for (int i = 0; i < 4; i++) dst4[tid + i * 256] = src[tid + i * 256];
    }
    __syncthreads();
    if (tid < 64) {
        const float* r = zs + tid * Dq;
        float s = 0.f;
#pragma unroll
        for (int d = 0; d < Dq; d++) s = fmaf(r[d], r[d], s);
        szz[tid] = s;
    }

    float bestv[8]; int besti[8];
#pragma unroll
    for (int i = 0; i < 8; i++) { bestv[i] = 3.0e38f; besti[i] = 0; }

    for (int kc = 0; kc < Kq; kc += 64) {
        // fill embed chunk, transposed to dpair-major (coalesced gmem reads)
        const float4* eg = (const float4*)(embed + (size_t)kc * Dq);
#pragma unroll
        for (int i = 0; i < 4; i++) {
            int id  = tid + i * 256;        // id = k*16 + seg
            int k   = id >> 4, seg = id & 15;
            float4 v = eg[id];
            es[(2 * seg)     * 65 + k] = make_float2(v.x, v.y);
            es[(2 * seg + 1) * 65 + k] = make_float2(v.z, v.w);
        }
        float ce0 = __ldg(&g_ce[kc + tx]);
        float ce1 = __ldg(&g_ce[kc + tx + 32]);
        __syncthreads();

        unsigned long long acc[8][2];
#pragma unroll
        for (int i = 0; i < 8; i++) { acc[i][0] = 0ull; acc[i][1] = 0ull; }

        const float* zrow = zs + ty * 8 * Dq;
#pragma unroll 8
        for (int dp = 0; dp < 32; dp++) {
            unsigned long long b0 = *(const unsigned long long*)&es[dp * 65 + tx];
            unsigned long long b1 = *(const unsigned long long*)&es[dp * 65 + tx + 32];
#pragma unroll
            for (int i = 0; i < 8; i++) {
                unsigned long long a =
                    *(const unsigned long long*)(zrow + i * Dq + 2 * dp);
                fma2(acc[i][0], a, b0);
                fma2(acc[i][1], a, b1);
            }
        }

#pragma unroll
        for (int i = 0; i < 8; i++) {
            float s  = szz[ty * 8 + i];
            float2 p0 = *(float2*)&acc[i][0];
            float2 p1 = *(float2*)&acc[i][1];
            // same association as reference: fl(fl(szz - 2*dot) + ce)
            float m0 = fmaf(-2.0f, p0.x + p0.y, s) + ce0;
            float m1 = fmaf(-2.0f, p1.x + p1.y, s) + ce1;
            if (m0 < bestv[i]) { bestv[i] = m0; besti[i] = kc + tx; }
            if (m1 < bestv[i]) { bestv[i] = m1; besti[i] = kc + tx + 32; }
        }
        __syncthreads();
    }

    // warp-reduce (tie-break: lowest index, matching jnp.argmax first-max)
#pragma unroll
    for (int i = 0; i < 8; i++) {
        float v = bestv[i]; int ix = besti[i];
#pragma unroll
        for (int o = 16; o; o >>= 1) {
            float ov = __shfl_xor_sync(0xffffffffu, v, o);
            int   oi = __shfl_xor_sync(0xffffffffu, ix, o);
            if (ov < v || (ov == v && oi < ix)) { v = ov; ix = oi; }
        }
        if (tx == 0) g_ind[n0 + ty * 8 + i] = ix;
    }
}

// ============================================================
// Kernel D: gather z_q, straight-through out (NCHW), ind, diff partials
// One thread per spatial position n.
// ============================================================
__global__ __launch_bounds__(256) void k_out(const float* __restrict__ embed,
                                             float* __restrict__ out, int out_size)
{
    __shared__ float red[256];
    int tid = threadIdx.x;
    int n   = blockIdx.x * 256 + tid;
    int b   = n >> 10, hw = n & 1023;
    int ind = g_ind[n];
    const float4* q4 = (const float4*)(embed + (size_t)ind * Dq);
    const float4* e4 = (const float4*)(g_ze + (size_t)n * Dq);
    float* ob = out + b * 65536 + hw;
    bool wrq = (out_size >= ZQ_ELEMS);
    float ss = 0.f;
#pragma unroll
    for (int i = 0; i < 16; i++) {
        float4 q = q4[i], e = e4[i];
        float dx = q.x - e.x, dy = q.y - e.y, dz = q.z - e.z, dw = q.w - e.w;
        ss += dx * dx + dy * dy + dz * dz + dw * dw;
        if (wrq) {
            // z_q_st = z_e + (z_q - z_e), out[b][d][h][w]
            ob[(4 * i + 0) * 1024] = e.x + dx;
            ob[(4 * i + 1) * 1024] = e.y + dy;
            ob[(4 * i + 2) * 1024] = e.z + dz;
            ob[(4 * i + 3) * 1024] = e.w + dw;
        }
    }
    if (out_size >= IND_OFF + Nq) out[IND_OFF + n] = (float)ind;

    red[tid] = ss;
    __syncthreads();
    for (int s = 128; s; s >>= 1) {
        if (tid < s) red[tid] += red[tid + s];
        __syncthreads();
    }
    if (tid == 0) g_part[blockIdx.x] = red[0];
}

// ============================================================
// Kernel E: deterministic final reduce -> diff scalar
// ============================================================
__global__ void k_diff(float* __restrict__ out, int out_size) {
    if (threadIdx.x == 0 && out_size >= DIFF_OFF + 1) {
        float s = 0.f;
        for (int i = 0; i < 64; i++) s += g_part[i];
        float m = s * (1.0f / 1048576.0f);           // mean over B*H*W*D
        out[DIFF_OFF] = 10.0f * (0.25f * m + m);     // KLD_SCALE*(COMMIT*m + m)
    }
}

extern "C" void kernel_launch(void* const* d_in, const int* in_sizes, int n_in,
                              void* d_out, int out_size)
{
    const float* z     = (const float*)d_in[0];   // [16,128,32,32]
    const float* pw    = (const float*)d_in[1];   // [64,128]
    const float* pb    = (const float*)d_in[2];   // [64]
    const float* gma   = (const float*)d_in[3];   // [64]
    const float* bta   = (const float*)d_in[4];   // [64]
    const float* rmn   = (const float*)d_in[5];   // [64]
    const float* rvr   = (const float*)d_in[6];   // [64]
    const float* embed = (const float*)d_in[7];   // [8192,64]
    float* out = (float*)d_out;

    k_proj  <<<Nq / 32, 256>>>(z, pw, pb, gma, bta, rmn, rvr);
    k_ce    <<<Kq / 8, 256>>>(embed);
    k_argmin<<<Nq / 64, 256>>>(embed);
    k_out   <<<Nq / 256, 256>>>(embed, out, out_size);
    k_diff  <<<1, 32>>>(out, out_size);
}

// round 4
// speedup vs baseline: 1.1915x; 1.1915x over previous
#include <cuda_runtime.h>
#include <cstdint>

// Problem constants
#define Bq  16
#define Cq  128
#define HWq 1024
#define Nq  16384   // B*H*W
#define Dq  64
#define Kq  8192

#define ZQ_ELEMS 1048576          // Nq*Dq  (z_q_st output, NCHW)
#define DIFF_OFF 1048576
#define IND_OFF  1048577

// ---- scratch (device globals; no allocation allowed) ----
__device__ float  g_ze[Nq * Dq];     // projected+BN z_e, row-major [N, D]
__device__ float4 g_et[16 * Kq];     // embed transposed: [seg=d/4][k] float4 (2 MB)
__device__ float  g_ce[Kq];          // ||e_k||^2
__device__ int    g_ind[Nq];         // argmin indices
__device__ float  g_part[256];       // per-block partial sums for diff

// Packed dual fp32 FMA (sm_10x): d.lo += a.lo*b.lo ; d.hi += a.hi*b.hi
__device__ __forceinline__ void fma2(unsigned long long& d,
                                     unsigned long long a,
                                     unsigned long long b) {
    asm("fma.rn.f32x2 %0, %1, %2, %3;" : "=l"(d) : "l"(a), "l"(b), "l"(d));
}

__device__ __forceinline__ void cpa16(uint32_t s, const void* g) {
    asm volatile("cp.async.ca.shared.global [%0], [%1], 16;" :: "r"(s), "l"(g));
}
#define CPA_COMMIT() asm volatile("cp.async.commit_group;")
#define CPA_WAIT1()  asm volatile("cp.async.wait_group 1;")

// ============================================================
// Kernel A: z_e = BN(conv1x1(z))   [N, D] fp32
// ============================================================
__global__ __launch_bounds__(256) void k_proj(
    const float* __restrict__ z,   const float* __restrict__ w,
    const float* __restrict__ pb,  const float* __restrict__ gma,
    const float* __restrict__ bta, const float* __restrict__ rmn,
    const float* __restrict__ rvr)
{
    __shared__ float zsm[Cq * 32];   // [c][nn]
    __shared__ float wsm[Dq * Cq];   // [d][c]
    int tid = threadIdx.x;
    int n0  = blockIdx.x * 32;
    int b   = n0 >> 10, hw0 = n0 & 1023;

#pragma unroll
    for (int i = 0; i < 16; i++) {
        int idx = tid + i * 256;
        int c = idx >> 5, nn = idx & 31;
        zsm[idx] = z[(b * Cq + c) * HWq + hw0 + nn];
    }
#pragma unroll
    for (int i = 0; i < 32; i++) wsm[tid + i * 256] = w[tid + i * 256];
    __syncthreads();

    int lane = tid & 31, wd = tid >> 5;
    int d0 = wd * 8;
    float acc[8];
#pragma unroll
    for (int j = 0; j < 8; j++) acc[j] = 0.f;

#pragma unroll 4
    for (int c = 0; c < Cq; c++) {
        float a = zsm[c * 32 + lane];
#pragma unroll
        for (int j = 0; j < 8; j++)
            acc[j] = fmaf(a, wsm[(d0 + j) * Cq + c], acc[j]);
    }

    float o[8];
#pragma unroll
    for (int j = 0; j < 8; j++) {
        int d = d0 + j;
        float sc = gma[d] * (1.0f / sqrtf(rvr[d] + 1e-5f));
        float sh = bta[d] - rmn[d] * sc;
        o[j] = (acc[j] + pb[d]) * sc + sh;
    }
    float* dst = g_ze + (size_t)(n0 + lane) * Dq + d0;
    ((float4*)dst)[0] = make_float4(o[0], o[1], o[2], o[3]);
    ((float4*)dst)[1] = make_float4(o[4], o[5], o[6], o[7]);
}

// ============================================================
// Kernel P: transpose embed -> g_et [seg][k], and ce[k]=||e_k||^2
// Thread per float4 (16 per code row). 16-lane shfl reduce for ce.
// ============================================================
__global__ __launch_bounds__(256) void k_prep(const float* __restrict__ embed)
{
    int id  = blockIdx.x * 256 + threadIdx.x;   // [0, Kq*16)
    int k   = id >> 4, seg = id & 15;
    float4 v = ((const float4*)embed)[id];
    g_et[seg * Kq + k] = v;
    float s = v.x * v.x + v.y * v.y + v.z * v.z + v.w * v.w;
    s += __shfl_xor_sync(0xffffffffu, s, 1);
    s += __shfl_xor_sync(0xffffffffu, s, 2);
    s += __shfl_xor_sync(0xffffffffu, s, 4);
    s += __shfl_xor_sync(0xffffffffu, s, 8);
    if (seg == 0) g_ce[k] = s;
}

// ============================================================
// Kernel C: argmin over K of (szz - 2*dot) + ce[k]
// 64 n-rows per CTA; 128-k chunks, cp.async double-buffered.
// Thread tile: 8n x 4k, f32x2 accumulators (64 FFMA2 / 12 LDS.128 per 2dp).
// ============================================================
__global__ __launch_bounds__(256, 2) void k_argmin(float* dummy)
{
    extern __shared__ float smem[];
    float*  zs  = smem;                       // 64*64 floats      (16384 B)
    float*  szz = smem + 4096;                // 64 floats (+pad to 16B)
    float4* es4 = (float4*)(smem + 4160);     // 2 bufs * 2048 f4  (65536 B)
    uint32_t es_u32 = (uint32_t)__cvta_generic_to_shared(es4);

    int tid = threadIdx.x;
    int tx  = tid & 31, ty = tid >> 5;
    int n0  = blockIdx.x * 64;

    // prologue: prefetch chunks 0 and 1
#pragma unroll
    for (int i = 0; i < 8; i++) {
        int id = tid + i * 256;
        int seg = id >> 7, kl = id & 127;
        cpa16(es_u32 + (uint32_t)id * 16u, &g_et[seg * Kq + kl]);
    }
    CPA_COMMIT();
#pragma unroll
    for (int i = 0; i < 8; i++) {
        int id = tid + i * 256;
        int seg = id >> 7, kl = id & 127;
        cpa16(es_u32 + (uint32_t)(2048 + id) * 16u, &g_et[seg * Kq + 128 + kl]);
    }
    CPA_COMMIT();

    {   // load z_e tile (4096 floats)
        const float4* src = (const float4*)(g_ze + (size_t)n0 * Dq);
        float4* dst4 = (float4*)zs;
#pragma unroll
        for (int i = 0; i < 4; i++) dst4[tid + i * 256] = src[tid + i * 256];
    }
    __syncthreads();
    if (tid < 64) {
        const float* r = zs + tid * Dq;
        float s = 0.f;
#pragma unroll
        for (int d = 0; d < Dq; d++) s = fmaf(r[d], r[d], s);
        szz[tid] = s;
    }

    float bestv[8]; int besti[8];
#pragma unroll
    for (int i = 0; i < 8; i++) { bestv[i] = 3.0e38f; besti[i] = 0; }

    const float* zrow = zs + ty * 8 * Dq;

    for (int c = 0; c < 64; c++) {
        CPA_WAIT1();
        __syncthreads();          // chunk c data + (c=0: szz) visible everywhere
        int buf = c & 1;
        const float4* eb = es4 + buf * 2048;

        float ce[4];
#pragma unroll
        for (int j = 0; j < 4; j++) ce[j] = __ldg(&g_ce[c * 128 + tx + 32 * j]);

        unsigned long long acc[8][4];
#pragma unroll
        for (int i = 0; i < 8; i++)
#pragma unroll
            for (int j = 0; j < 4; j++) acc[i][j] = 0ull;

#pragma unroll
        for (int dp2 = 0; dp2 < 16; dp2++) {
            unsigned long long b01[4], b23[4];
#pragma unroll
            for (int j = 0; j < 4; j++) {
                float4 b = eb[dp2 * 128 + tx + 32 * j];
                b01[j] = *(unsigned long long*)&b.x;
                b23[j] = *(unsigned long long*)&b.z;
            }
#pragma unroll
            for (int i = 0; i < 8; i++) {
                float4 a = *(const float4*)(zrow + i * Dq + dp2 * 4);
                unsigned long long a01 = *(unsigned long long*)&a.x;
                unsigned long long a23 = *(unsigned long long*)&a.z;
#pragma unroll
                for (int j = 0; j < 4; j++) {
                    fma2(acc[i][j], a01, b01[j]);
                    fma2(acc[i][j], a23, b23[j]);
                }
            }
        }

#pragma unroll
        for (int i = 0; i < 8; i++) {
            float s = szz[ty * 8 + i];
#pragma unroll
            for (int j = 0; j < 4; j++) {
                float2 p = *(float2*)&acc[i][j];
                // same rounding chain as reference: fl(szz - 2*dot) + ce
                float m = fmaf(-2.0f, p.x + p.y, s) + ce[j];
                if (m < bestv[i]) { bestv[i] = m; besti[i] = c * 128 + tx + 32 * j; }
            }
        }
        __syncthreads();          // everyone done reading buf before refill

        if (c + 2 < 64) {
#pragma unroll
            for (int i = 0; i < 8; i++) {
                int id = tid + i * 256;
                int seg = id >> 7, kl = id & 127;
                cpa16(es_u32 + (uint32_t)(buf * 2048 + id) * 16u,
                      &g_et[seg * Kq + (c + 2) * 128 + kl]);
            }
        }
        CPA_COMMIT();             // always commit (possibly empty) for wait accounting
    }

    // warp-reduce (tie-break: lowest index, matching jnp.argmax first-max)
#pragma unroll
    for (int i = 0; i < 8; i++) {
        float v = bestv[i]; int ix = besti[i];
#pragma unroll
        for (int o = 16; o; o >>= 1) {
            float ov = __shfl_xor_sync(0xffffffffu, v, o);
            int   oi = __shfl_xor_sync(0xffffffffu, ix, o);
            if (ov < v || (ov == v && oi < ix)) { v = ov; ix = oi; }
        }
        if (tx == 0) g_ind[n0 + ty * 8 + i] = ix;
    }
}

// ============================================================
// Kernel D: gather z_q, straight-through out (NCHW), ind, diff partials
// One thread per spatial position n. 256 CTAs x 64 threads (SM coverage).
// ============================================================
__global__ __launch_bounds__(64) void k_out(const float* __restrict__ embed,
                                            float* __restrict__ out, int out_size)
{
    __shared__ float red[64];
    int tid = threadIdx.x;
    int n   = blockIdx.x * 64 + tid;
    int b   = n >> 10, hw = n & 1023;
    int ind = g_ind[n];
    const float4* q4 = (const float4*)(embed + (size_t)ind * Dq);
    const float4* e4 = (const float4*)(g_ze + (size_t)n * Dq);
    float* ob = out + b * 65536 + hw;
    bool wrq = (out_size >= ZQ_ELEMS);
    float ss = 0.f;
#pragma unroll
    for (int i = 0; i < 16; i++) {
        float4 q = q4[i], e = e4[i];
        float dx = q.x - e.x, dy = q.y - e.y, dz = q.z - e.z, dw = q.w - e.w;
        ss += dx * dx + dy * dy + dz * dz + dw * dw;
        if (wrq) {
            ob[(4 * i + 0) * 1024] = e.x + dx;
            ob[(4 * i + 1) * 1024] = e.y + dy;
            ob[(4 * i + 2) * 1024] = e.z + dz;
            ob[(4 * i + 3) * 1024] = e.w + dw;
        }
    }
    if (out_size >= IND_OFF + Nq) out[IND_OFF + n] = (float)ind;

    red[tid] = ss;
    __syncthreads();
    for (int s = 32; s; s >>= 1) {
        if (tid < s) red[tid] += red[tid + s];
        __syncthreads();
    }
    if (tid == 0) g_part[blockIdx.x] = red[0];
}

// ============================================================
// Kernel E: deterministic final reduce -> diff scalar
// ============================================================
__global__ void k_diff(float* __restrict__ out, int out_size) {
    if (threadIdx.x == 0 && out_size >= DIFF_OFF + 1) {
        float s = 0.f;
        for (int i = 0; i < 256; i++) s += g_part[i];
        float m = s * (1.0f / 1048576.0f);           // mean over B*H*W*D
        out[DIFF_OFF] = 10.0f * (0.25f * m + m);     // KLD_SCALE*(COMMIT*m + m)
    }
}

extern "C" void kernel_launch(void* const* d_in, const int* in_sizes, int n_in,
                              void* d_out, int out_size)
{
    const float* z     = (const float*)d_in[0];   // [16,128,32,32]
    const float* pw    = (const float*)d_in[1];   // [64,128]
    const float* pb    = (const float*)d_in[2];   // [64]
    const float* gma   = (const float*)d_in[3];   // [64]
    const float* bta   = (const float*)d_in[4];   // [64]
    const float* rmn   = (const float*)d_in[5];   // [64]
    const float* rvr   = (const float*)d_in[6];   // [64]
    const float* embed = (const float*)d_in[7];   // [8192,64]
    float* out = (float*)d_out;

    static const int kArgSmem = 4160 * 4 + 2 * 2048 * 16;   // 82176 B
    cudaFuncSetAttribute(k_argmin, cudaFuncAttributeMaxDynamicSharedMemorySize,
                         kArgSmem);

    k_proj  <<<Nq / 32, 256>>>(z, pw, pb, gma, bta, rmn, rvr);
    k_prep  <<<Kq * 16 / 256, 256>>>(embed);
    k_argmin<<<Nq / 64, 256, kArgSmem>>>(out);
    k_out   <<<Nq / 64, 64>>>(embed, out, out_size);
    k_diff  <<<1, 32>>>(out, out_size);
}